// round 12
// baseline (speedup 1.0000x reference)
#include <cuda_runtime.h>
#include <cuda_bf16.h>
#include <cstdint>

// DeepSpeed fixed sparse self-attention, B=2, H=16, S=2048, D=64, fp32.
// q-rows [64t,64t+64) attend window keys [64t,64t+48) + stripes [64m+48,64m+64).
// Math: mma.sync m16n8k16 bf16, 3-MMA split compensation (R8/R11-verified).
// R12: software pipeline ACROSS tiles inside each warp: issue QK(t+1) before
// softmax(t)+PV(t) so tensor MMAs interleave with MUFU/FMA softmax.
// 3-stage cp.async ring (stage t+2 issued one full pass ahead).
// 128-thread CTAs, 112KB smem, 2 CTAs/SM.

#define SEQ 2048
#define HD  64
#define NBH 32
#define NEGBIG (-1e30f)
#define SC2 0.18033688011112042f   // 0.125 * log2(e)

// smem layout (bytes): Q hi/lo then 3 stages
#define SM_QH 0
#define SM_QL 8192
#define SM_S0 16384
#define STG   32768                 // stage: KH +0, KL +8192, VH +16384, VL +24576
#define SM_TOTAL (16384 + 3 * STG)  // 114688

__device__ __align__(16) __nv_bfloat16 g_Kh[(size_t)NBH*SEQ*HD];
__device__ __align__(16) __nv_bfloat16 g_Kl[(size_t)NBH*SEQ*HD];
__device__ __align__(16) __nv_bfloat16 g_Vh[(size_t)NBH*SEQ*HD];
__device__ __align__(16) __nv_bfloat16 g_Vl[(size_t)NBH*SEQ*HD];

__device__ __forceinline__ void mma_bf16(float4& d,
                                         uint32_t a0, uint32_t a1, uint32_t a2, uint32_t a3,
                                         uint32_t b0, uint32_t b1)
{
    asm volatile(
        "mma.sync.aligned.m16n8k16.row.col.f32.bf16.bf16.f32 "
        "{%0,%1,%2,%3}, {%4,%5,%6,%7}, {%8,%9}, {%0,%1,%2,%3};\n"
        : "+f"(d.x), "+f"(d.y), "+f"(d.z), "+f"(d.w)
        : "r"(a0), "r"(a1), "r"(a2), "r"(a3), "r"(b0), "r"(b1));
}

__device__ __forceinline__ void ldsm_x4(uint32_t& r0, uint32_t& r1, uint32_t& r2, uint32_t& r3,
                                        uint32_t addr)
{
    asm volatile("ldmatrix.sync.aligned.m8n8.x4.shared.b16 {%0,%1,%2,%3}, [%4];"
                 : "=r"(r0), "=r"(r1), "=r"(r2), "=r"(r3) : "r"(addr));
}

__device__ __forceinline__ void ldsm_x4_t(uint32_t& r0, uint32_t& r1, uint32_t& r2, uint32_t& r3,
                                          uint32_t addr)
{
    asm volatile("ldmatrix.sync.aligned.m8n8.x4.trans.shared.b16 {%0,%1,%2,%3}, [%4];"
                 : "=r"(r0), "=r"(r1), "=r"(r2), "=r"(r3) : "r"(addr));
}

__device__ __forceinline__ void split2(float a, float b, uint32_t& h, uint32_t& l)
{
    __nv_bfloat162 hv = __floats2bfloat162_rn(a, b);
    h = *reinterpret_cast<uint32_t*>(&hv);
    float ra = a - __bfloat162float(hv.x);
    float rb = b - __bfloat162float(hv.y);
    __nv_bfloat162 lv = __floats2bfloat162_rn(ra, rb);
    l = *reinterpret_cast<uint32_t*>(&lv);
}

__device__ __forceinline__ void cp16(uint32_t dst, const void* src)
{
    asm volatile("cp.async.ca.shared.global [%0], [%1], 16;\n" :: "r"(dst), "l"(src));
}
__device__ __forceinline__ void cp_commit()
{
    asm volatile("cp.async.commit_group;\n" ::: "memory");
}
template<int N> __device__ __forceinline__ void cp_wait()
{
    asm volatile("cp.async.wait_group %0;\n" :: "n"(N) : "memory");
}

// ================= prepass: split K,V into bf16 hi/lo =================
__global__ void prepass_split(const float* __restrict__ K, const float* __restrict__ V, int n8)
{
    int i = blockIdx.x * blockDim.x + threadIdx.x;
    if (i >= n8) return;
    const float4* K4 = reinterpret_cast<const float4*>(K);
    const float4* V4 = reinterpret_cast<const float4*>(V);
    uint32_t h0,l0,h1,l1,h2,l2,h3,l3;

    float4 a = K4[2*i], b = K4[2*i+1];
    split2(a.x,a.y,h0,l0); split2(a.z,a.w,h1,l1);
    split2(b.x,b.y,h2,l2); split2(b.z,b.w,h3,l3);
    reinterpret_cast<uint4*>(g_Kh)[i] = make_uint4(h0,h1,h2,h3);
    reinterpret_cast<uint4*>(g_Kl)[i] = make_uint4(l0,l1,l2,l3);

    a = V4[2*i]; b = V4[2*i+1];
    split2(a.x,a.y,h0,l0); split2(a.z,a.w,h1,l1);
    split2(b.x,b.y,h2,l2); split2(b.z,b.w,h3,l3);
    reinterpret_cast<uint4*>(g_Vh)[i] = make_uint4(h0,h1,h2,h3);
    reinterpret_cast<uint4*>(g_Vl)[i] = make_uint4(l0,l1,l2,l3);
}

// ---- cp.async staging of one 64-key tile (K+V, hi+lo) ----
__device__ __forceinline__ void stage_cp(uint32_t kvb, int tbase, int sp, bool window,
                                         const uint4* gkh, const uint4* gkl,
                                         const uint4* gvh, const uint4* gvl, int tid)
{
    #pragma unroll
    for (int it = 0; it < 4; it++) {
        int idx = tid + it * 128;              // 0..511
        int row = idx >> 3, ch = idx & 7;
        int gk = window ? (tbase + row)
                        : ((sp * 4 + (row >> 4)) * 64 + 48 + (row & 15));
        size_t go = (size_t)gk * 8 + ch;
        uint32_t sw = (uint32_t)(row * 128 + ((ch ^ (row & 7)) << 4));
        cp16(kvb + sw,          gkh + go);
        cp16(kvb + 8192 + sw,   gkl + go);
        cp16(kvb + 16384 + sw,  gvh + go);
        cp16(kvb + 24576 + sw,  gvl + go);
    }
}

// ================= QK MMAs for one tile (R8-verified maps) =================
template<int NTP>
__device__ __forceinline__ void qk_tile(uint32_t smb, uint32_t kvb, float4 (&s)[8],
                                        int lane, int warp)
{
    const int arow  = (warp << 4) + (((lane >> 3) & 1) << 3) + (lane & 7);
    const int krow0 = ((lane >> 4) << 3) + (lane & 7);
    const int kchp  = (lane >> 3) & 1;

    #pragma unroll
    for (int i = 0; i < 2 * NTP; i++) s[i] = make_float4(0.f, 0.f, 0.f, 0.f);

    #pragma unroll
    for (int kb = 0; kb < 4; kb++) {
        const int qch = kb * 2 + (lane >> 4);
        const uint32_t qa = smb + SM_QH + arow * 128 + ((qch ^ (arow & 7)) << 4);
        uint32_t ah0, ah1, ah2, ah3, al0, al1, al2, al3;
        ldsm_x4(ah0, ah1, ah2, ah3, qa);
        ldsm_x4(al0, al1, al2, al3, qa + (SM_QL - SM_QH));
        #pragma unroll
        for (int ntp = 0; ntp < NTP; ntp++) {
            const int krow = ntp * 16 + krow0;
            const int kch  = kb * 2 + kchp;
            const uint32_t ka = kvb + krow * 128 + ((kch ^ (krow & 7)) << 4);
            uint32_t bh0, bh1, bh2, bh3, bl0, bl1, bl2, bl3;
            ldsm_x4(bh0, bh1, bh2, bh3, ka + 8192);   // K lo
            ldsm_x4(bl0, bl1, bl2, bl3, ka);          // K hi
            mma_bf16(s[2 * ntp],     ah0, ah1, ah2, ah3, bh0, bh1);   // Qh*Kl
            mma_bf16(s[2 * ntp],     al0, al1, al2, al3, bl0, bl1);   // Ql*Kh
            mma_bf16(s[2 * ntp],     ah0, ah1, ah2, ah3, bl0, bl1);   // Qh*Kh
            mma_bf16(s[2 * ntp + 1], ah0, ah1, ah2, ah3, bh2, bh3);
            mma_bf16(s[2 * ntp + 1], al0, al1, al2, al3, bl2, bl3);
            mma_bf16(s[2 * ntp + 1], ah0, ah1, ah2, ah3, bl2, bl3);
        }
    }
}

// ================= softmax + PV for one tile (R8-verified maps) =================
template<int NTP, int KBPV, bool FIRST>
__device__ __forceinline__ void smax_pv(
    float4 (&s)[8], uint32_t kvb, float4 (&o)[8],
    float& m0, float& m1, float& l0, float& l1, int lane)
{
    const int vrow0 = (((lane >> 3) & 1) << 3) + (lane & 7);
    const int vchp  = lane >> 4;

    float rm0 = NEGBIG, rm1 = NEGBIG;
    #pragma unroll
    for (int nt = 0; nt < 2 * NTP; nt++) {
        s[nt].x *= SC2; s[nt].y *= SC2; s[nt].z *= SC2; s[nt].w *= SC2;
        rm0 = fmaxf(rm0, fmaxf(s[nt].x, s[nt].y));
        rm1 = fmaxf(rm1, fmaxf(s[nt].z, s[nt].w));
    }
    rm0 = fmaxf(rm0, __shfl_xor_sync(0xffffffffu, rm0, 1));
    rm0 = fmaxf(rm0, __shfl_xor_sync(0xffffffffu, rm0, 2));
    rm1 = fmaxf(rm1, __shfl_xor_sync(0xffffffffu, rm1, 1));
    rm1 = fmaxf(rm1, __shfl_xor_sync(0xffffffffu, rm1, 2));

    float mn0, mn1;
    if (FIRST) { mn0 = rm0; mn1 = rm1; }
    else       { mn0 = fmaxf(m0, rm0); mn1 = fmaxf(m1, rm1); }

    float rs0 = 0.f, rs1 = 0.f;
    #pragma unroll
    for (int nt = 0; nt < 2 * NTP; nt++) {
        s[nt].x = exp2f(s[nt].x - mn0);
        s[nt].y = exp2f(s[nt].y - mn0);
        s[nt].z = exp2f(s[nt].z - mn1);
        s[nt].w = exp2f(s[nt].w - mn1);
        rs0 += s[nt].x + s[nt].y;
        rs1 += s[nt].z + s[nt].w;
    }
    rs0 += __shfl_xor_sync(0xffffffffu, rs0, 1);
    rs0 += __shfl_xor_sync(0xffffffffu, rs0, 2);
    rs1 += __shfl_xor_sync(0xffffffffu, rs1, 1);
    rs1 += __shfl_xor_sync(0xffffffffu, rs1, 2);

    if (FIRST) {
        l0 = rs0; l1 = rs1; m0 = mn0; m1 = mn1;
    } else {
        const float alp0 = exp2f(m0 - mn0), alp1 = exp2f(m1 - mn1);
        m0 = mn0; m1 = mn1;
        l0 = l0 * alp0 + rs0;
        l1 = l1 * alp1 + rs1;
        #pragma unroll
        for (int dt = 0; dt < 8; dt++) {
            o[dt].x *= alp0; o[dt].y *= alp0;
            o[dt].z *= alp1; o[dt].w *= alp1;
        }
    }

    #pragma unroll
    for (int kb = 0; kb < KBPV; kb++) {
        uint32_t ah0, al0_, ah1, al1_, ah2, al2_, ah3, al3_;
        split2(s[2 * kb].x,     s[2 * kb].y,     ah0, al0_);
        split2(s[2 * kb].z,     s[2 * kb].w,     ah1, al1_);
        split2(s[2 * kb + 1].x, s[2 * kb + 1].y, ah2, al2_);
        split2(s[2 * kb + 1].z, s[2 * kb + 1].w, ah3, al3_);
        const int vrow = kb * 16 + vrow0;
        #pragma unroll
        for (int dtp = 0; dtp < 4; dtp++) {
            const int vch = dtp * 2 + vchp;
            const uint32_t va = kvb + 16384 + vrow * 128 + ((vch ^ (vrow & 7)) << 4);
            uint32_t bh0, bh1, bh2, bh3, bl0, bl1, bl2, bl3;
            ldsm_x4_t(bh0, bh1, bh2, bh3, va);          // V hi
            ldsm_x4_t(bl0, bl1, bl2, bl3, va + 8192);   // V lo
            mma_bf16(o[2 * dtp],     ah0, ah1, ah2, ah3, bl0, bl1);     // Ph*Vl
            mma_bf16(o[2 * dtp],     al0_, al1_, al2_, al3_, bh0, bh1); // Pl*Vh
            mma_bf16(o[2 * dtp],     ah0, ah1, ah2, ah3, bh0, bh1);     // Ph*Vh
            mma_bf16(o[2 * dtp + 1], ah0, ah1, ah2, ah3, bl2, bl3);
            mma_bf16(o[2 * dtp + 1], al0_, al1_, al2_, al3_, bh2, bh3);
            mma_bf16(o[2 * dtp + 1], ah0, ah1, ah2, ah3, bh2, bh3);
        }
    }
}

// ================= main kernel =================
__global__ void __launch_bounds__(128, 2)
sparse_attn_bf16(const float* __restrict__ Q, float* __restrict__ Out)
{
    extern __shared__ __align__(16) char sm[];
    const uint32_t smb = (uint32_t)__cvta_generic_to_shared(sm);

    const int tid  = threadIdx.x;
    const int warp = tid >> 5;
    const int lane = tid & 31;
    const int g    = lane >> 2;
    const int q4   = lane & 3;
    const int t    = blockIdx.x;          // q tile 0..31
    const int bh   = blockIdx.y;

    const size_t base = (size_t)bh * SEQ * HD;
    const float* Qg = Q + base + (size_t)t * 64 * HD;
    float*       Og = Out + base + (size_t)t * 64 * HD;
    const uint4* gkh = reinterpret_cast<const uint4*>(g_Kh + base);
    const uint4* gkl = reinterpret_cast<const uint4*>(g_Kl + base);
    const uint4* gvh = reinterpret_cast<const uint4*>(g_Vh + base);
    const uint4* gvl = reinterpret_cast<const uint4*>(g_Vl + base);

    uint32_t b_cur = smb + SM_S0;
    uint32_t b_nxt = smb + SM_S0 + STG;
    uint32_t b_stg = smb + SM_S0 + 2 * STG;

    // issue tile0 (window) and tile1 (stripe 0)
    stage_cp(b_cur, t * 64, 0, true,  gkh, gkl, gvh, gvl, tid);
    cp_commit();
    stage_cp(b_nxt, 0,      0, false, gkh, gkl, gvh, gvl, tid);
    cp_commit();

    // ---- stage Q hi/lo while tiles fly ----
    #pragma unroll
    for (int it = 0; it < 4; it++) {
        int idx = tid + it * 128;             // 0..511
        int r = idx >> 3, ch = idx & 7;
        const float4* src = reinterpret_cast<const float4*>(Qg + r * HD + ch * 8);
        float4 a = src[0], b = src[1];
        uint32_t h0,l0,h1,l1,h2,l2,h3,l3;
        split2(a.x,a.y,h0,l0); split2(a.z,a.w,h1,l1);
        split2(b.x,b.y,h2,l2); split2(b.z,b.w,h3,l3);
        uint32_t sw = (uint32_t)(r * 128 + ((ch ^ (r & 7)) << 4));
        *reinterpret_cast<uint4*>(sm + SM_QH + sw) = make_uint4(h0,h1,h2,h3);
        *reinterpret_cast<uint4*>(sm + SM_QL + sw) = make_uint4(l0,l1,l2,l3);
    }

    float4 o[8];
    #pragma unroll
    for (int i = 0; i < 8; i++) o[i] = make_float4(0.f, 0.f, 0.f, 0.f);
    float m0 = 0.f, m1 = 0.f, l0 = 0.f, l1 = 0.f;
    const int r0 = warp * 16 + g;

    float4 s_cur[8], s_nxt[8];

    // ---- prologue: QK(0) ----
    cp_wait<1>();          // tile0 complete
    __syncthreads();
    qk_tile<3>(smb, b_cur, s_cur, lane, warp);

    // ---- iteration 0 (tile0 = window) ----
    stage_cp(b_stg, 0, 1, false, gkh, gkl, gvh, gvl, tid);   // tile2
    cp_commit();
    cp_wait<1>();          // tile1 complete
    __syncthreads();
    qk_tile<4>(smb, b_nxt, s_nxt, lane, warp);               // QK(1)
    smax_pv<3, 3, true>(s_cur, b_cur, o, m0, m1, l0, l1, lane);  // softmax+PV(0)
    __syncthreads();
    { uint32_t tmp = b_cur; b_cur = b_nxt; b_nxt = b_stg; b_stg = tmp; }
    #pragma unroll
    for (int i = 0; i < 8; i++) s_cur[i] = s_nxt[i];

    // ---- iterations 1..8 (stripe tiles) ----
    for (int p = 1; p < 9; p++) {
        if (p <= 6)
            stage_cp(b_stg, 0, p + 1, false, gkh, gkl, gvh, gvl, tid);  // tile p+2
        cp_commit();
        cp_wait<1>();
        __syncthreads();
        if (p < 8)
            qk_tile<4>(smb, b_nxt, s_nxt, lane, warp);       // QK(p+1)
        smax_pv<4, 4, false>(s_cur, b_cur, o, m0, m1, l0, l1, lane);  // softmax+PV(p)
        __syncthreads();
        { uint32_t tmp = b_cur; b_cur = b_nxt; b_nxt = b_stg; b_stg = tmp; }
        #pragma unroll
        for (int i = 0; i < 8; i++) s_cur[i] = s_nxt[i];
    }

    // ---- epilogue ----
    const float inv0 = 1.f / l0, inv1 = 1.f / l1;
    #pragma unroll
    for (int dt = 0; dt < 8; dt++) {
        *reinterpret_cast<float2*>(Og + r0 * HD + dt * 8 + 2 * q4) =
            make_float2(o[dt].x * inv0, o[dt].y * inv0);
        *reinterpret_cast<float2*>(Og + (r0 + 8) * HD + dt * 8 + 2 * q4) =
            make_float2(o[dt].z * inv1, o[dt].w * inv1);
    }
}

extern "C" void kernel_launch(void* const* d_in, const int* in_sizes, int n_in,
                              void* d_out, int out_size)
{
    const float* Q = (const float*)d_in[0];
    const float* K = (const float*)d_in[1];
    const float* V = (const float*)d_in[2];
    float* O = (float*)d_out;

    const int nbh = in_sizes[0] / (SEQ * HD);      // 32
    const int n8  = nbh * SEQ * HD / 8;
    prepass_split<<<(n8 + 255) / 256, 256>>>(K, V, n8);

    cudaFuncSetAttribute(sparse_attn_bf16,
                         cudaFuncAttributeMaxDynamicSharedMemorySize, SM_TOTAL);
    dim3 grid(SEQ / 64, nbh);
    sparse_attn_bf16<<<grid, 128, SM_TOTAL>>>(Q, O);
}

// round 14
// speedup vs baseline: 1.0803x; 1.0803x over previous
#include <cuda_runtime.h>
#include <cuda_bf16.h>
#include <cstdint>

// DeepSpeed fixed sparse self-attention, B=2, H=16, S=2048, D=64, fp32.
// q-rows [64t,64t+64) attend window [64t,64t+48) + stripes [64m+48,64m+64), m=0..31.
// Math: mma.sync m16n8k16 bf16, 3-MMA split compensation (verified path).
// R14: 32-key chunks, CORRECT count: 18 chunks = 32+16 window + 16x(2 stripes).
// Double-buffered 16KB stages, cp.async one chunk ahead, ONE sync per chunk.
// 4 CTAs/SM x 128 thr = 16 warps/SM.

#define SEQ 2048
#define HD  64
#define NBH 32
#define NEGBIG (-1e30f)
#define SC2 0.18033688011112042f   // 0.125 * log2(e)

// smem (bytes): Q hi/lo (64 rows x 128B each), then 2 stages.
// stage: KH +0, KL +4096, VH +8192, VL +12288 (32 rows x 128B each)
#define SM_QH 0
#define SM_QL 8192
#define SM_S0 16384
#define STG   16384
#define SM_TOTAL 49152

__device__ __align__(16) __nv_bfloat16 g_Kh[(size_t)NBH*SEQ*HD];
__device__ __align__(16) __nv_bfloat16 g_Kl[(size_t)NBH*SEQ*HD];
__device__ __align__(16) __nv_bfloat16 g_Vh[(size_t)NBH*SEQ*HD];
__device__ __align__(16) __nv_bfloat16 g_Vl[(size_t)NBH*SEQ*HD];

__device__ __forceinline__ void mma_bf16(float4& d,
                                         uint32_t a0, uint32_t a1, uint32_t a2, uint32_t a3,
                                         uint32_t b0, uint32_t b1)
{
    asm volatile(
        "mma.sync.aligned.m16n8k16.row.col.f32.bf16.bf16.f32 "
        "{%0,%1,%2,%3}, {%4,%5,%6,%7}, {%8,%9}, {%0,%1,%2,%3};\n"
        : "+f"(d.x), "+f"(d.y), "+f"(d.z), "+f"(d.w)
        : "r"(a0), "r"(a1), "r"(a2), "r"(a3), "r"(b0), "r"(b1));
}

__device__ __forceinline__ void ldsm_x4(uint32_t& r0, uint32_t& r1, uint32_t& r2, uint32_t& r3,
                                        uint32_t addr)
{
    asm volatile("ldmatrix.sync.aligned.m8n8.x4.shared.b16 {%0,%1,%2,%3}, [%4];"
                 : "=r"(r0), "=r"(r1), "=r"(r2), "=r"(r3) : "r"(addr));
}

__device__ __forceinline__ void ldsm_x4_t(uint32_t& r0, uint32_t& r1, uint32_t& r2, uint32_t& r3,
                                          uint32_t addr)
{
    asm volatile("ldmatrix.sync.aligned.m8n8.x4.trans.shared.b16 {%0,%1,%2,%3}, [%4];"
                 : "=r"(r0), "=r"(r1), "=r"(r2), "=r"(r3) : "r"(addr));
}

__device__ __forceinline__ void split2(float a, float b, uint32_t& h, uint32_t& l)
{
    __nv_bfloat162 hv = __floats2bfloat162_rn(a, b);
    h = *reinterpret_cast<uint32_t*>(&hv);
    float ra = a - __bfloat162float(hv.x);
    float rb = b - __bfloat162float(hv.y);
    __nv_bfloat162 lv = __floats2bfloat162_rn(ra, rb);
    l = *reinterpret_cast<uint32_t*>(&lv);
}

__device__ __forceinline__ void cp16(uint32_t dst, const void* src)
{
    asm volatile("cp.async.ca.shared.global [%0], [%1], 16;\n" :: "r"(dst), "l"(src));
}
__device__ __forceinline__ void cp_commit()
{
    asm volatile("cp.async.commit_group;\n" ::: "memory");
}
__device__ __forceinline__ void cp_wait_all()
{
    asm volatile("cp.async.wait_group 0;\n" ::: "memory");
}

// ================= prepass: split K,V into bf16 hi/lo =================
__global__ void prepass_split(const float* __restrict__ K, const float* __restrict__ V, int n8)
{
    int i = blockIdx.x * blockDim.x + threadIdx.x;
    if (i >= n8) return;
    const float4* K4 = reinterpret_cast<const float4*>(K);
    const float4* V4 = reinterpret_cast<const float4*>(V);
    uint32_t h0,l0,h1,l1,h2,l2,h3,l3;

    float4 a = K4[2*i], b = K4[2*i+1];
    split2(a.x,a.y,h0,l0); split2(a.z,a.w,h1,l1);
    split2(b.x,b.y,h2,l2); split2(b.z,b.w,h3,l3);
    reinterpret_cast<uint4*>(g_Kh)[i] = make_uint4(h0,h1,h2,h3);
    reinterpret_cast<uint4*>(g_Kl)[i] = make_uint4(l0,l1,l2,l3);

    a = V4[2*i]; b = V4[2*i+1];
    split2(a.x,a.y,h0,l0); split2(a.z,a.w,h1,l1);
    split2(b.x,b.y,h2,l2); split2(b.z,b.w,h3,l3);
    reinterpret_cast<uint4*>(g_Vh)[i] = make_uint4(h0,h1,h2,h3);
    reinterpret_cast<uint4*>(g_Vl)[i] = make_uint4(l0,l1,l2,l3);
}

// ---- cp.async staging of chunk c: c0 = window keys 0..31, c1 = window 32..47,
//      c in [2,18) = stripes 2(c-2), 2(c-2)+1 (keys 64m+48..64m+63 each) ----
__device__ __forceinline__ void stage_cp(uint32_t kvb, int c, int t,
                                         const uint4* gkh, const uint4* gkl,
                                         const uint4* gvh, const uint4* gvl, int tid)
{
    #pragma unroll
    for (int it = 0; it < 2; it++) {
        int idx = tid + it * 128;              // 0..255
        int row = idx >> 3, ch = idx & 7;      // row 0..31
        if (c == 1 && row >= 16) break;        // half chunk
        int gk;
        if (c == 0)      gk = t * 64 + row;
        else if (c == 1) gk = t * 64 + 32 + row;
        else {
            int stripe = 2 * (c - 2) + (row >> 4);   // 0..31
            gk = stripe * 64 + 48 + (row & 15);
        }
        size_t go = (size_t)gk * 8 + ch;
        uint32_t sw = (uint32_t)(row * 128 + ((ch ^ (row & 7)) << 4));
        cp16(kvb + sw,          gkh + go);
        cp16(kvb + 4096 + sw,   gkl + go);
        cp16(kvb + 8192 + sw,   gvh + go);
        cp16(kvb + 12288 + sw,  gvl + go);
    }
}

// ================= per-chunk compute (verified fragment maps) =================
// NTP: x4 K-fragment pairs (1 => 16 keys, 2 => 32 keys).
template<int NTP, bool FIRST>
__device__ __forceinline__ void compute_chunk(
    uint32_t smb, uint32_t kvb, float4 (&o)[8],
    float& m0, float& m1, float& l0, float& l1, int lane, int warp)
{
    const int arow  = (warp << 4) + (((lane >> 3) & 1) << 3) + (lane & 7);
    const int krow0 = ((lane >> 4) << 3) + (lane & 7);
    const int kchp  = (lane >> 3) & 1;
    const int vrow0 = (((lane >> 3) & 1) << 3) + (lane & 7);
    const int vchp  = lane >> 4;

    float4 s[2 * NTP];
    #pragma unroll
    for (int i = 0; i < 2 * NTP; i++) s[i] = make_float4(0.f, 0.f, 0.f, 0.f);

    // ---- QK ----
    #pragma unroll
    for (int kb = 0; kb < 4; kb++) {
        const int qch = kb * 2 + (lane >> 4);
        const uint32_t qa = smb + SM_QH + arow * 128 + ((qch ^ (arow & 7)) << 4);
        uint32_t ah0, ah1, ah2, ah3, al0, al1, al2, al3;
        ldsm_x4(ah0, ah1, ah2, ah3, qa);
        ldsm_x4(al0, al1, al2, al3, qa + (SM_QL - SM_QH));
        #pragma unroll
        for (int ntp = 0; ntp < NTP; ntp++) {
            const int krow = ntp * 16 + krow0;
            const int kch  = kb * 2 + kchp;
            const uint32_t ka = kvb + krow * 128 + ((kch ^ (krow & 7)) << 4);
            uint32_t kl0, kl1, kl2, kl3, kh0, kh1, kh2, kh3;
            ldsm_x4(kl0, kl1, kl2, kl3, ka + 4096);   // K lo
            ldsm_x4(kh0, kh1, kh2, kh3, ka);          // K hi
            mma_bf16(s[2 * ntp],     ah0, ah1, ah2, ah3, kl0, kl1);   // Qh*Kl
            mma_bf16(s[2 * ntp],     al0, al1, al2, al3, kh0, kh1);   // Ql*Kh
            mma_bf16(s[2 * ntp],     ah0, ah1, ah2, ah3, kh0, kh1);   // Qh*Kh
            mma_bf16(s[2 * ntp + 1], ah0, ah1, ah2, ah3, kl2, kl3);
            mma_bf16(s[2 * ntp + 1], al0, al1, al2, al3, kh2, kh3);
            mma_bf16(s[2 * ntp + 1], ah0, ah1, ah2, ah3, kh2, kh3);
        }
    }

    // ---- streaming softmax (base-2) ----
    float rm0 = NEGBIG, rm1 = NEGBIG;
    #pragma unroll
    for (int nt = 0; nt < 2 * NTP; nt++) {
        s[nt].x *= SC2; s[nt].y *= SC2; s[nt].z *= SC2; s[nt].w *= SC2;
        rm0 = fmaxf(rm0, fmaxf(s[nt].x, s[nt].y));
        rm1 = fmaxf(rm1, fmaxf(s[nt].z, s[nt].w));
    }
    rm0 = fmaxf(rm0, __shfl_xor_sync(0xffffffffu, rm0, 1));
    rm0 = fmaxf(rm0, __shfl_xor_sync(0xffffffffu, rm0, 2));
    rm1 = fmaxf(rm1, __shfl_xor_sync(0xffffffffu, rm1, 1));
    rm1 = fmaxf(rm1, __shfl_xor_sync(0xffffffffu, rm1, 2));

    float mn0, mn1;
    if (FIRST) { mn0 = rm0; mn1 = rm1; }
    else       { mn0 = fmaxf(m0, rm0); mn1 = fmaxf(m1, rm1); }

    float rs0 = 0.f, rs1 = 0.f;
    #pragma unroll
    for (int nt = 0; nt < 2 * NTP; nt++) {
        s[nt].x = exp2f(s[nt].x - mn0);
        s[nt].y = exp2f(s[nt].y - mn0);
        s[nt].z = exp2f(s[nt].z - mn1);
        s[nt].w = exp2f(s[nt].w - mn1);
        rs0 += s[nt].x + s[nt].y;
        rs1 += s[nt].z + s[nt].w;
    }
    rs0 += __shfl_xor_sync(0xffffffffu, rs0, 1);
    rs0 += __shfl_xor_sync(0xffffffffu, rs0, 2);
    rs1 += __shfl_xor_sync(0xffffffffu, rs1, 1);
    rs1 += __shfl_xor_sync(0xffffffffu, rs1, 2);

    if (FIRST) {
        l0 = rs0; l1 = rs1; m0 = mn0; m1 = mn1;
    } else {
        const float alp0 = exp2f(m0 - mn0), alp1 = exp2f(m1 - mn1);
        m0 = mn0; m1 = mn1;
        l0 = l0 * alp0 + rs0;
        l1 = l1 * alp1 + rs1;
        #pragma unroll
        for (int dt = 0; dt < 8; dt++) {
            o[dt].x *= alp0; o[dt].y *= alp0;
            o[dt].z *= alp1; o[dt].w *= alp1;
        }
    }

    // ---- PV ----
    #pragma unroll
    for (int kb = 0; kb < NTP; kb++) {
        uint32_t ph0, pl0, ph1, pl1, ph2, pl2, ph3, pl3;
        split2(s[2 * kb].x,     s[2 * kb].y,     ph0, pl0);
        split2(s[2 * kb].z,     s[2 * kb].w,     ph1, pl1);
        split2(s[2 * kb + 1].x, s[2 * kb + 1].y, ph2, pl2);
        split2(s[2 * kb + 1].z, s[2 * kb + 1].w, ph3, pl3);
        const int vrow = kb * 16 + vrow0;
        #pragma unroll
        for (int dtp = 0; dtp < 4; dtp++) {
            const int vch = dtp * 2 + vchp;
            const uint32_t va = kvb + 8192 + vrow * 128 + ((vch ^ (vrow & 7)) << 4);
            uint32_t vh0, vh1, vh2, vh3, vl0, vl1, vl2, vl3;
            ldsm_x4_t(vh0, vh1, vh2, vh3, va);          // V hi
            ldsm_x4_t(vl0, vl1, vl2, vl3, va + 4096);   // V lo
            mma_bf16(o[2 * dtp],     ph0, ph1, ph2, ph3, vl0, vl1);   // Ph*Vl
            mma_bf16(o[2 * dtp],     pl0, pl1, pl2, pl3, vh0, vh1);   // Pl*Vh
            mma_bf16(o[2 * dtp],     ph0, ph1, ph2, ph3, vh0, vh1);   // Ph*Vh
            mma_bf16(o[2 * dtp + 1], ph0, ph1, ph2, ph3, vl2, vl3);
            mma_bf16(o[2 * dtp + 1], pl0, pl1, pl2, pl3, vh2, vh3);
            mma_bf16(o[2 * dtp + 1], ph0, ph1, ph2, ph3, vh2, vh3);
        }
    }
}

// ================= main kernel =================
__global__ void __launch_bounds__(128, 4)
sparse_attn_bf16(const float* __restrict__ Q, float* __restrict__ Out)
{
    extern __shared__ __align__(16) char sm[];
    const uint32_t smb = (uint32_t)__cvta_generic_to_shared(sm);

    const int tid  = threadIdx.x;
    const int warp = tid >> 5;
    const int lane = tid & 31;
    const int g    = lane >> 2;
    const int q4   = lane & 3;
    const int t    = blockIdx.x;          // q tile 0..31
    const int bh   = blockIdx.y;

    const size_t base = (size_t)bh * SEQ * HD;
    const float* Qg = Q + base + (size_t)t * 64 * HD;
    float*       Og = Out + base + (size_t)t * 64 * HD;
    const uint4* gkh = reinterpret_cast<const uint4*>(g_Kh + base);
    const uint4* gkl = reinterpret_cast<const uint4*>(g_Kl + base);
    const uint4* gvh = reinterpret_cast<const uint4*>(g_Vh + base);
    const uint4* gvl = reinterpret_cast<const uint4*>(g_Vl + base);

    // issue chunk0 immediately
    stage_cp(smb + SM_S0, 0, t, gkh, gkl, gvh, gvl, tid);
    cp_commit();

    // ---- stage Q hi/lo while chunk0 flies ----
    #pragma unroll
    for (int it = 0; it < 4; it++) {
        int idx = tid + it * 128;             // 0..511
        int r = idx >> 3, ch = idx & 7;
        const float4* src = reinterpret_cast<const float4*>(Qg + r * HD + ch * 8);
        float4 a = src[0], b = src[1];
        uint32_t h0,l0,h1,l1,h2,l2,h3,l3;
        split2(a.x,a.y,h0,l0); split2(a.z,a.w,h1,l1);
        split2(b.x,b.y,h2,l2); split2(b.z,b.w,h3,l3);
        uint32_t sw = (uint32_t)(r * 128 + ((ch ^ (r & 7)) << 4));
        *reinterpret_cast<uint4*>(sm + SM_QH + sw) = make_uint4(h0,h1,h2,h3);
        *reinterpret_cast<uint4*>(sm + SM_QL + sw) = make_uint4(l0,l1,l2,l3);
    }

    float4 o[8];
    #pragma unroll
    for (int i = 0; i < 8; i++) o[i] = make_float4(0.f, 0.f, 0.f, 0.f);
    float m0 = 0.f, m1 = 0.f, l0 = 0.f, l1 = 0.f;
    const int r0 = warp * 16 + g;

    // ---- 18 chunks, one sync each, cp.async one chunk ahead ----
    #pragma unroll 1
    for (int c = 0; c < 18; c++) {
        cp_wait_all();
        __syncthreads();     // chunk c visible; compute(c-1) done -> other buffer free
        if (c < 17)
            stage_cp(smb + SM_S0 + ((c + 1) & 1) * STG, c + 1, t,
                     gkh, gkl, gvh, gvl, tid);
        cp_commit();
        const uint32_t kvb = smb + SM_S0 + (c & 1) * STG;
        if (c == 0)      compute_chunk<2, true >(smb, kvb, o, m0, m1, l0, l1, lane, warp);
        else if (c == 1) compute_chunk<1, false>(smb, kvb, o, m0, m1, l0, l1, lane, warp);
        else             compute_chunk<2, false>(smb, kvb, o, m0, m1, l0, l1, lane, warp);
    }

    // ---- epilogue ----
    const float inv0 = 1.f / l0, inv1 = 1.f / l1;
    #pragma unroll
    for (int dt = 0; dt < 8; dt++) {
        *reinterpret_cast<float2*>(Og + r0 * HD + dt * 8 + 2 * q4) =
            make_float2(o[dt].x * inv0, o[dt].y * inv0);
        *reinterpret_cast<float2*>(Og + (r0 + 8) * HD + dt * 8 + 2 * q4) =
            make_float2(o[dt].z * inv1, o[dt].w * inv1);
    }
}

extern "C" void kernel_launch(void* const* d_in, const int* in_sizes, int n_in,
                              void* d_out, int out_size)
{
    const float* Q = (const float*)d_in[0];
    const float* K = (const float*)d_in[1];
    const float* V = (const float*)d_in[2];
    float* O = (float*)d_out;

    const int nbh = in_sizes[0] / (SEQ * HD);      // 32
    const int n8  = nbh * SEQ * HD / 8;
    prepass_split<<<(n8 + 255) / 256, 256>>>(K, V, n8);

    cudaFuncSetAttribute(sparse_attn_bf16,
                         cudaFuncAttributeMaxDynamicSharedMemorySize, SM_TOTAL);
    dim3 grid(SEQ / 64, nbh);
    sparse_attn_bf16<<<grid, 128, SM_TOTAL>>>(Q, O);
}